// round 9
// baseline (speedup 1.0000x reference)
#include <cuda_runtime.h>
#include <math.h>

#define NN 65536
#define EE 1048576
#define CC 101
#define BNEPS 1e-5f

// ---------------- device scratch (no allocations allowed) ----------------
__device__ float  g_z[NN * 128];      // z = concat[x,pos] @ Wl   (up to 2 fused convs)
__device__ float  g_m[NN * 128];      // agg for cls/obj stage only
__device__ float  g_h1[NN * 64];      // pre-BN conv outputs
__device__ float  g_h2[NN * 64];
__device__ float  g_h3[NN * 64];
__device__ int    g_deg[NN];
__device__ int    g_rowptr[NN + 1];
__device__ int    g_cursor[NN];
__device__ int    g_col[EE];
__device__ int    g_bsum[256];
__device__ double g_sum[192];
__device__ double g_sumsq[192];

// ---------------- f32x2 helpers (Blackwell packed fp32) ----------------
typedef unsigned long long u64;
__device__ __forceinline__ u64 pk2(float x, float y) {
    u64 r; asm("mov.b64 %0,{%1,%2};" : "=l"(r) : "f"(x), "f"(y)); return r;
}
__device__ __forceinline__ void upk2(u64 v, float& x, float& y) {
    asm("mov.b64 {%0,%1},%2;" : "=f"(x), "=f"(y) : "l"(v));
}
__device__ __forceinline__ u64 f2fma(u64 a, u64 b, u64 c) {
    u64 d; asm("fma.rn.f32x2 %0,%1,%2,%3;" : "=l"(d) : "l"(a), "l"(b), "l"(c)); return d;
}
__device__ __forceinline__ u64 f2add(u64 a, u64 b) {
    u64 d; asm("add.rn.f32x2 %0,%1,%2;" : "=l"(d) : "l"(a), "l"(b)); return d;
}

// ---------------- CSR build ----------------
__global__ void zero_kernel() {
    int i = blockIdx.x * blockDim.x + threadIdx.x;
    if (i < NN) g_deg[i] = 0;
    if (i < 192) { g_sum[i] = 0.0; g_sumsq[i] = 0.0; }
}
__global__ void deg_kernel(const int* __restrict__ dst) {
    int e = blockIdx.x * blockDim.x + threadIdx.x;
    if (e < EE) atomicAdd(&g_deg[dst[e]], 1);
}
__global__ void scan1_kernel() {   // 256 blocks x 256 thr: per-block inclusive scan
    __shared__ int sm[256];
    int b = blockIdx.x, t = threadIdx.x, i = b * 256 + t;
    int v = g_deg[i]; sm[t] = v; __syncthreads();
    for (int off = 1; off < 256; off <<= 1) {
        int x = (t >= off) ? sm[t - off] : 0;
        __syncthreads(); sm[t] += x; __syncthreads();
    }
    g_rowptr[i] = sm[t] - v;
    if (t == 255) g_bsum[b] = sm[t];
}
__global__ void scan23_kernel() {  // merged: each block scans bsum itself, then offsets
    __shared__ int sm[256];
    int b = blockIdx.x, t = threadIdx.x, i = b * 256 + t;
    sm[t] = g_bsum[t]; __syncthreads();
    for (int off = 1; off < 256; off <<= 1) {
        int x = (t >= off) ? sm[t - off] : 0;
        __syncthreads(); sm[t] += x; __syncthreads();
    }
    int pre = (b == 0) ? 0 : sm[b - 1];
    int r = g_rowptr[i] + pre;
    g_rowptr[i] = r; g_cursor[i] = r;
    if (i == 0) g_rowptr[NN] = EE;
}
__global__ void fill_kernel(const int* __restrict__ src, const int* __restrict__ dst) {
    int e = blockIdx.x * blockDim.x + threadIdx.x;
    if (e < EE) {
        int p = atomicAdd(&g_cursor[dst[e]], 1);
        g_col[p] = src[e];
    }
}

// ---------------- z-GEMM: Z[i, half*64+c] = concat[T(X[i]), pos[i]] @ W_half ----------------
// If stats_off >= 0: T(x) = relu(x*s + t) with s,t computed inline from BN stats (bnfin fused).
__global__ void __launch_bounds__(256, 1) zgemm_kernel(
    const float* __restrict__ X, const float* __restrict__ pos,
    const float* __restrict__ Wa, const float* __restrict__ Wb,
    const float* __restrict__ gamma, const float* __restrict__ beta, int stats_off,
    float* __restrict__ Z, int halves)
{
    __shared__ u64 dup[8][2][64];
    int warp = threadIdx.x >> 5, lane = threadIdx.x & 31;
    int gw = blockIdx.x * 8 + warp;
    int nw = gridDim.x * 8;
    int ntask = NN * halves;
    int Ct = halves << 6;
    bool hasT = (stats_off >= 0);
    float s0 = 0.f, s1 = 0.f, t0 = 0.f, t1 = 0.f;
    if (hasT) {
        double m0 = g_sum[stats_off + 2 * lane] / (double)NN;
        double q0 = g_sumsq[stats_off + 2 * lane] / (double)NN - m0 * m0;
        double m1 = g_sum[stats_off + 2 * lane + 1] / (double)NN;
        double q1 = g_sumsq[stats_off + 2 * lane + 1] / (double)NN - m1 * m1;
        s0 = gamma[2 * lane]     * rsqrtf((float)q0 + BNEPS);
        s1 = gamma[2 * lane + 1] * rsqrtf((float)q1 + BNEPS);
        t0 = beta[2 * lane]     - (float)m0 * s0;
        t1 = beta[2 * lane + 1] - (float)m1 * s1;
    }
    u64 Wreg[66];
    int curhalf = -1;
    int par = 0;
    for (int task = gw; task < ntask; task += nw) {
        int half = task >> 16;
        int node = task & (NN - 1);
        if (half != curhalf) {
            curhalf = half;
            const float* W = half ? Wb : Wa;
            #pragma unroll
            for (int k = 0; k < 66; k++)
                Wreg[k] = *(const u64*)(W + (size_t)k * 64 + 2 * lane);
        }
        float2 a = *(const float2*)(X + (size_t)node * 64 + 2 * lane);
        if (hasT) {
            a.x = fmaxf(fmaf(a.x, s0, t0), 0.f);
            a.y = fmaxf(fmaf(a.y, s1, t1), 0.f);
        }
        dup[warp][par][2 * lane]     = pk2(a.x, a.x);
        dup[warp][par][2 * lane + 1] = pk2(a.y, a.y);
        __syncwarp();
        u64 acc0 = 0ull, acc1 = 0ull, acc2 = 0ull, acc3 = 0ull;
        #pragma unroll
        for (int k = 0; k < 64; k += 4) {
            acc0 = f2fma(Wreg[k],     dup[warp][par][k],     acc0);
            acc1 = f2fma(Wreg[k + 1], dup[warp][par][k + 1], acc1);
            acc2 = f2fma(Wreg[k + 2], dup[warp][par][k + 2], acc2);
            acc3 = f2fma(Wreg[k + 3], dup[warp][par][k + 3], acc3);
        }
        float2 p = *(const float2*)(pos + (size_t)node * 2);
        acc0 = f2fma(Wreg[64], pk2(p.x, p.x), acc0);
        acc1 = f2fma(Wreg[65], pk2(p.y, p.y), acc1);
        u64 r = f2add(f2add(acc0, acc1), f2add(acc2, acc3));
        float rx, ry; upk2(r, rx, ry);
        float2 o; o.x = rx; o.y = ry;
        *(float2*)(Z + (size_t)node * Ct + (half << 6) + 2 * lane) = o;
        par ^= 1;
    }
}

// ---------------- gather-max of one 64-ch half-row (unroll 8), minus pos term ----------------
__device__ __forceinline__ float2 gather_max(
    const float* __restrict__ zr, int node, int Ct,
    const float* __restrict__ Wl, const float* __restrict__ pos, int lane)
{
    float2 m = *(const float2*)(zr + (size_t)node * Ct);   // self-loop
    int beg = g_rowptr[node], end = g_rowptr[node + 1];
    int j = beg;
    for (; j + 8 <= end; j += 8) {
        int i0 = g_col[j], i1 = g_col[j+1], i2 = g_col[j+2], i3 = g_col[j+3];
        int i4 = g_col[j+4], i5 = g_col[j+5], i6 = g_col[j+6], i7 = g_col[j+7];
        float2 v0 = *(const float2*)(zr + (size_t)i0 * Ct);
        float2 v1 = *(const float2*)(zr + (size_t)i1 * Ct);
        float2 v2 = *(const float2*)(zr + (size_t)i2 * Ct);
        float2 v3 = *(const float2*)(zr + (size_t)i3 * Ct);
        float2 v4 = *(const float2*)(zr + (size_t)i4 * Ct);
        float2 v5 = *(const float2*)(zr + (size_t)i5 * Ct);
        float2 v6 = *(const float2*)(zr + (size_t)i6 * Ct);
        float2 v7 = *(const float2*)(zr + (size_t)i7 * Ct);
        float ax = fmaxf(fmaxf(v0.x, v1.x), fmaxf(v2.x, v3.x));
        float bx = fmaxf(fmaxf(v4.x, v5.x), fmaxf(v6.x, v7.x));
        float ay = fmaxf(fmaxf(v0.y, v1.y), fmaxf(v2.y, v3.y));
        float by = fmaxf(fmaxf(v4.y, v5.y), fmaxf(v6.y, v7.y));
        m.x = fmaxf(m.x, fmaxf(ax, bx));
        m.y = fmaxf(m.y, fmaxf(ay, by));
    }
    for (; j < end; j++) {
        int s = g_col[j];
        float2 v = *(const float2*)(zr + (size_t)s * Ct);
        m.x = fmaxf(m.x, v.x); m.y = fmaxf(m.y, v.y);
    }
    float2 w0 = *(const float2*)(Wl + 64 * 64 + 2 * lane);
    float2 w1 = *(const float2*)(Wl + 65 * 64 + 2 * lane);
    float2 p = *(const float2*)(pos + (size_t)node * 2);
    m.x -= p.x * w0.x + p.y * w1.x;
    m.y -= p.x * w0.y + p.y * w1.y;
    return m;
}

// ---------------- FUSED segmax + mgemm (COUT=64) + BN stats ----------------
__global__ void __launch_bounds__(256, 1) fsegmm_kernel(
    const float* __restrict__ Z, const float* __restrict__ pos,
    const float* __restrict__ Wla, const float* __restrict__ Wlb,
    const float* __restrict__ W2a, const float* __restrict__ W2b,
    float* __restrict__ OUTa, float* __restrict__ OUTb,
    int statsA, int statsB, int halves)
{
    __shared__ u64 dup[8][2][64];
    int warp = threadIdx.x >> 5, lane = threadIdx.x & 31;
    int gw = blockIdx.x * 8 + warp;
    int nw = gridDim.x * 8;
    int ntask = NN * halves;
    int Ct = halves << 6;
    u64 Wreg[64];
    const float* Wl = Wla;
    float* OUT = OUTa;
    int curhalf = -1, curstats = -1, par = 0;
    float ls0 = 0.f, lq0 = 0.f, ls1 = 0.f, lq1 = 0.f;
    for (int task = gw; task < ntask; task += nw) {
        int half = task >> 16;
        int node = task & (NN - 1);
        if (half != curhalf) {
            if (curstats >= 0) {
                atomicAdd(&g_sum[curstats + 2 * lane],     (double)ls0);
                atomicAdd(&g_sum[curstats + 2 * lane + 1], (double)ls1);
                atomicAdd(&g_sumsq[curstats + 2 * lane],     (double)lq0);
                atomicAdd(&g_sumsq[curstats + 2 * lane + 1], (double)lq1);
                ls0 = lq0 = ls1 = lq1 = 0.f;
            }
            curhalf = half;
            const float* W2 = half ? W2b : W2a;
            #pragma unroll
            for (int k = 0; k < 64; k++)
                Wreg[k] = *(const u64*)(W2 + (size_t)k * 64 + 2 * lane);
            Wl = half ? Wlb : Wla;
            OUT = half ? OUTb : OUTa;
            curstats = half ? statsB : statsA;
        }
        const float* zr = Z + (half << 6) + 2 * lane;
        float2 m = gather_max(zr, node, Ct, Wl, pos, lane);
        dup[warp][par][2 * lane]     = pk2(m.x, m.x);
        dup[warp][par][2 * lane + 1] = pk2(m.y, m.y);
        __syncwarp();
        u64 acc0 = 0ull, acc1 = 0ull, acc2 = 0ull, acc3 = 0ull;
        #pragma unroll
        for (int k = 0; k < 64; k += 4) {
            acc0 = f2fma(Wreg[k],     dup[warp][par][k],     acc0);
            acc1 = f2fma(Wreg[k + 1], dup[warp][par][k + 1], acc1);
            acc2 = f2fma(Wreg[k + 2], dup[warp][par][k + 2], acc2);
            acc3 = f2fma(Wreg[k + 3], dup[warp][par][k + 3], acc3);
        }
        u64 r = f2add(f2add(acc0, acc1), f2add(acc2, acc3));
        float rx, ry; upk2(r, rx, ry);
        ls0 += rx; lq0 += rx * rx;
        ls1 += ry; lq1 += ry * ry;
        float2 o; o.x = rx; o.y = ry;
        *(float2*)(OUT + (size_t)node * 64 + 2 * lane) = o;
        par ^= 1;
    }
    if (curstats >= 0) {
        atomicAdd(&g_sum[curstats + 2 * lane],     (double)ls0);
        atomicAdd(&g_sum[curstats + 2 * lane + 1], (double)ls1);
        atomicAdd(&g_sumsq[curstats + 2 * lane],     (double)lq0);
        atomicAdd(&g_sumsq[curstats + 2 * lane + 1], (double)lq1);
    }
}

// ---------------- FUSED segmax + 4-channel head (reg) ----------------
__global__ void fseghead4_kernel(
    const float* __restrict__ Z, const float* __restrict__ pos,
    const float* __restrict__ Wl, const float* __restrict__ W2 /*[64,4]*/,
    const float* __restrict__ bias, float* __restrict__ OUT)
{
    int gw = (blockIdx.x * blockDim.x + threadIdx.x) >> 5;
    int lane = threadIdx.x & 31;
    if (gw >= NN) return;
    float4 wa = *(const float4*)(W2 + (size_t)(2 * lane) * 4);
    float4 wb = *(const float4*)(W2 + (size_t)(2 * lane + 1) * 4);
    int node = gw;
    const float* zr = Z + 2 * lane;
    float2 m = gather_max(zr, node, 64, Wl, pos, lane);
    float p0 = m.x * wa.x + m.y * wb.x;
    float p1 = m.x * wa.y + m.y * wb.y;
    float p2 = m.x * wa.z + m.y * wb.z;
    float p3 = m.x * wa.w + m.y * wb.w;
    #pragma unroll
    for (int o = 16; o > 0; o >>= 1) {
        p0 += __shfl_xor_sync(0xffffffff, p0, o);
        p1 += __shfl_xor_sync(0xffffffff, p1, o);
        p2 += __shfl_xor_sync(0xffffffff, p2, o);
        p3 += __shfl_xor_sync(0xffffffff, p3, o);
    }
    if (lane == 0) {
        float4 r;
        r.x = p0 + bias[0]; r.y = p1 + bias[1];
        r.z = p2 + bias[2]; r.w = p3 + bias[3];
        *(float4*)(OUT + (size_t)node * 4) = r;
    }
}

// ---------------- segment max (writes M; cls/obj stage) ----------------
__global__ void segmax_kernel(
    const float* __restrict__ Z, const float* __restrict__ pos,
    const float* __restrict__ Wa, const float* __restrict__ Wb,
    float* __restrict__ M, int halves)
{
    int gw = (blockIdx.x * blockDim.x + threadIdx.x) >> 5;
    int lane = threadIdx.x & 31;
    int nw = (gridDim.x * blockDim.x) >> 5;
    int ntask = NN * halves;
    int Ct = halves << 6;
    for (int task = gw; task < ntask; task += nw) {
        int half = task >> 16;
        int node = task & (NN - 1);
        int coff = (half << 6) + 2 * lane;
        const float* zr = Z + coff;
        const float* Wl = half ? Wb : Wa;
        float2 m = gather_max(zr, node, Ct, Wl, pos, lane);
        *(float2*)(M + (size_t)node * Ct + coff) = m;
    }
}

// ---------------- m-GEMM (cls head, COUT=101 over 2 output-halves) ----------------
__global__ void __launch_bounds__(256, 1) mgemm_kernel(
    const float* __restrict__ M, int Cin, int inoff,
    const float* __restrict__ W, int COUT,
    const float* __restrict__ bias,
    float* __restrict__ OUT, int ostride, int halves)
{
    __shared__ u64 dup[8][2][64];
    int warp = threadIdx.x >> 5, lane = threadIdx.x & 31;
    int gw = blockIdx.x * 8 + warp;
    int nw = gridDim.x * 8;
    int ntask = NN * halves;
    u64 Wreg[64];
    int curhalf = -1;
    int c0 = 0; bool v0 = false, v1 = false;
    float bx = 0.f, by = 0.f;
    int par = 0;
    for (int task = gw; task < ntask; task += nw) {
        int half = task >> 16;
        int node = task & (NN - 1);
        if (half != curhalf) {
            curhalf = half;
            c0 = (half << 6) + 2 * lane;
            v0 = (c0 < COUT); v1 = (c0 + 1 < COUT);
            #pragma unroll
            for (int k = 0; k < 64; k++) {
                float wx = v0 ? W[(size_t)k * COUT + c0] : 0.f;
                float wy = v1 ? W[(size_t)k * COUT + c0 + 1] : 0.f;
                Wreg[k] = pk2(wx, wy);
            }
            bx = (bias && v0) ? bias[c0] : 0.f;
            by = (bias && v1) ? bias[c0 + 1] : 0.f;
        }
        float2 a = *(const float2*)(M + (size_t)node * Cin + inoff + 2 * lane);
        dup[warp][par][2 * lane]     = pk2(a.x, a.x);
        dup[warp][par][2 * lane + 1] = pk2(a.y, a.y);
        __syncwarp();
        u64 acc0 = 0ull, acc1 = 0ull, acc2 = 0ull, acc3 = 0ull;
        #pragma unroll
        for (int k = 0; k < 64; k += 4) {
            acc0 = f2fma(Wreg[k],     dup[warp][par][k],     acc0);
            acc1 = f2fma(Wreg[k + 1], dup[warp][par][k + 1], acc1);
            acc2 = f2fma(Wreg[k + 2], dup[warp][par][k + 2], acc2);
            acc3 = f2fma(Wreg[k + 3], dup[warp][par][k + 3], acc3);
        }
        u64 r = f2add(f2add(acc0, acc1), f2add(acc2, acc3));
        float rx, ry; upk2(r, rx, ry);
        rx += bx; ry += by;
        if (v0) OUT[(size_t)node * ostride + c0] = rx;
        if (v1) OUT[(size_t)node * ostride + c0 + 1] = ry;
        par ^= 1;
    }
}

// ---------------- tiny-output head (obj, COUT=1) ----------------
template <int COUT>
__global__ void head_kernel(const float* __restrict__ M, int Cin, int inoff,
                            const float* __restrict__ W, const float* __restrict__ bias,
                            float* __restrict__ OUT, int ostride)
{
    __shared__ float Ws[64 * COUT];
    for (int i = threadIdx.x; i < 64 * COUT; i += blockDim.x) Ws[i] = W[i];
    __syncthreads();
    int node = blockIdx.x * blockDim.x + threadIdx.x;
    if (node >= NN) return;
    float acc[COUT];
    #pragma unroll
    for (int c = 0; c < COUT; c++) acc[c] = bias[c];
    const float* a = M + (size_t)node * Cin + inoff;
    #pragma unroll 8
    for (int k = 0; k < 64; k++) {
        float av = a[k];
        #pragma unroll
        for (int c = 0; c < COUT; c++) acc[c] = fmaf(av, Ws[k * COUT + c], acc[c]);
    }
    #pragma unroll
    for (int c = 0; c < COUT; c++) OUT[(size_t)node * ostride + c] = acc[c];
}

// ---------------- host orchestration ----------------
static void* symaddr(const void* symbol) {
    void* p = nullptr;
    cudaGetSymbolAddress(&p, symbol);
    return p;
}

extern "C" void kernel_launch(void* const* d_in, const int* in_sizes, int n_in,
                              void* d_out, int out_size)
{
    const float* x   = (const float*)d_in[0];
    const float* pos = (const float*)d_in[1];
    const int*   ei  = (const int*)d_in[2];
    const float* W11 = (const float*)d_in[3];  const float* W12 = (const float*)d_in[4];
    const float* g1  = (const float*)d_in[5];  const float* b1  = (const float*)d_in[6];
    const float* W21 = (const float*)d_in[7];  const float* W22 = (const float*)d_in[8];
    const float* g2  = (const float*)d_in[9];  const float* b2  = (const float*)d_in[10];
    const float* W31 = (const float*)d_in[11]; const float* W32 = (const float*)d_in[12];
    const float* g3  = (const float*)d_in[13]; const float* b3  = (const float*)d_in[14];
    const float* Wr1 = (const float*)d_in[15]; const float* Wr2 = (const float*)d_in[16];
    const float* br2 = (const float*)d_in[17];
    const float* Wc1 = (const float*)d_in[18]; const float* Wc2 = (const float*)d_in[19];
    const float* bc2 = (const float*)d_in[20];
    const float* Wo1 = (const float*)d_in[21]; const float* Wo2 = (const float*)d_in[22];
    const float* bo2 = (const float*)d_in[23];
    float* out = (float*)d_out;

    const int* src = ei;
    const int* dst = ei + EE;

    float* Z  = (float*)symaddr(g_z);
    float* M  = (float*)symaddr(g_m);
    float* H1 = (float*)symaddr(g_h1);
    float* H2 = (float*)symaddr(g_h2);
    float* H3 = (float*)symaddr(g_h3);

    const int GB = 296;

    // ---- CSR build (zgemm1 interleaved at slot 4 so ncu captures it) ----
    zero_kernel<<<NN / 256, 256>>>();
    deg_kernel<<<EE / 256, 256>>>(dst);
    scan1_kernel<<<256, 256>>>();
    zgemm_kernel<<<GB, 256>>>(x, pos, W11, nullptr, nullptr, nullptr, -1, Z, 1);  // slot 4
    scan23_kernel<<<256, 256>>>();
    fill_kernel<<<EE / 256, 256>>>(src, dst);

    // ---- conv1: fused segmax+mgemm -> H1, stats@0 ----
    fsegmm_kernel<<<GB, 256>>>(Z, pos, W11, nullptr, W12, nullptr, H1, nullptr, 0, -1, 1);

    // ---- conv2 + conv3 fused: x1 = relu(bn1(h1)) inline ----
    zgemm_kernel<<<GB, 256>>>(H1, pos, W21, W31, g1, b1, 0, Z, 2);
    fsegmm_kernel<<<GB, 256>>>(Z, pos, W21, W31, W22, W32, H2, H3, 64, 128, 2);

    // ---- reg head: x2 = relu(bn2(h2)) inline -> out[N*101..] ----
    zgemm_kernel<<<GB, 256>>>(H2, pos, Wr1, nullptr, g2, b2, 64, Z, 1);
    fseghead4_kernel<<<NN / 8, 256>>>(Z, pos, Wr1, Wr2, br2, out + (size_t)NN * CC);

    // ---- cls + obj heads: x3 = relu(bn3(h3)) inline ----
    zgemm_kernel<<<GB, 256>>>(H3, pos, Wc1, Wo1, g3, b3, 128, Z, 2);
    segmax_kernel<<<NN * 2 / 8, 256>>>(Z, pos, Wc1, Wo1, M, 2);
    mgemm_kernel<<<GB, 256>>>(M, 128, 0, Wc2, CC, bc2, out, CC, 2);
    head_kernel<1><<<NN / 256, 256>>>(M, 128, 64, Wo2, bo2, out + (size_t)NN * (CC + 4), 1);

    (void)in_sizes; (void)n_in; (void)out_size;
}

// round 14
// speedup vs baseline: 1.3040x; 1.3040x over previous
#include <cuda_runtime.h>
#include <math.h>

#define NN 65536
#define EE 1048576
#define CC 101
#define BNEPS 1e-5f

// ---------------- device scratch ----------------
__device__ float  g_z[NN * 128];
__device__ float  g_m[NN * 128];
__device__ float  g_h1[NN * 64];
__device__ float  g_h2[NN * 64];
__device__ float  g_h3[NN * 64];
__device__ int    g_deg[NN];
__device__ int    g_rowptr[NN + 1];
__device__ int    g_cursor[NN];
__device__ int    g_col[EE];
__device__ int    g_bsum[256];
__device__ double g_sum[192];
__device__ double g_sumsq[192];

// ---------------- f32x2 helpers ----------------
typedef unsigned long long u64;
__device__ __forceinline__ u64 pk2(float x, float y) {
    u64 r; asm("mov.b64 %0,{%1,%2};" : "=l"(r) : "f"(x), "f"(y)); return r;
}
__device__ __forceinline__ void upk2(u64 v, float& x, float& y) {
    asm("mov.b64 {%0,%1},%2;" : "=f"(x), "=f"(y) : "l"(v));
}
__device__ __forceinline__ u64 f2fma(u64 a, u64 b, u64 c) {
    u64 d; asm("fma.rn.f32x2 %0,%1,%2,%3;" : "=l"(d) : "l"(a), "l"(b), "l"(c)); return d;
}
__device__ __forceinline__ u64 f2add(u64 a, u64 b) {
    u64 d; asm("add.rn.f32x2 %0,%1,%2;" : "=l"(d) : "l"(a), "l"(b)); return d;
}

// ---------------- CSR build ----------------
__global__ void zero_kernel() {
    int i = blockIdx.x * blockDim.x + threadIdx.x;
    if (i < NN) g_deg[i] = 0;
    if (i < 192) { g_sum[i] = 0.0; g_sumsq[i] = 0.0; }
}
__global__ void deg_kernel(const int* __restrict__ dst) {
    int e = blockIdx.x * blockDim.x + threadIdx.x;
    if (e < EE) atomicAdd(&g_deg[dst[e]], 1);
}
__global__ void scan1_kernel() {
    __shared__ int sm[256];
    int b = blockIdx.x, t = threadIdx.x, i = b * 256 + t;
    int v = g_deg[i]; sm[t] = v; __syncthreads();
    for (int off = 1; off < 256; off <<= 1) {
        int x = (t >= off) ? sm[t - off] : 0;
        __syncthreads(); sm[t] += x; __syncthreads();
    }
    g_rowptr[i] = sm[t] - v;
    if (t == 255) g_bsum[b] = sm[t];
}
__global__ void scan23_kernel() {
    __shared__ int sm[256];
    int b = blockIdx.x, t = threadIdx.x, i = b * 256 + t;
    sm[t] = g_bsum[t]; __syncthreads();
    for (int off = 1; off < 256; off <<= 1) {
        int x = (t >= off) ? sm[t - off] : 0;
        __syncthreads(); sm[t] += x; __syncthreads();
    }
    int pre = (b == 0) ? 0 : sm[b - 1];
    int r = g_rowptr[i] + pre;
    g_rowptr[i] = r; g_cursor[i] = r;
    if (i == 0) g_rowptr[NN] = EE;
}
__global__ void fill_kernel(const int* __restrict__ src, const int* __restrict__ dst) {
    int e = blockIdx.x * blockDim.x + threadIdx.x;
    if (e < EE) {
        int p = atomicAdd(&g_cursor[dst[e]], 1);
        g_col[p] = src[e];
    }
}

// ---------------- split-k z-GEMM: pair of warps per task ----------------
// warp kh=0: k 0..31; warp kh=1: k 32..63 + pos rows. Partial combine via smem + named bar.
__global__ void __launch_bounds__(256, 2) zgemm_kernel(
    const float* __restrict__ X, const float* __restrict__ pos,
    const float* __restrict__ Wa, const float* __restrict__ Wb,
    const float* __restrict__ gamma, const float* __restrict__ beta, int stats_off,
    float* __restrict__ Z, int halves)
{
    __shared__ u64 dup[8][2][32];
    __shared__ u64 pbuf[4][2][32];
    int tid = threadIdx.x, warp = tid >> 5, lane = tid & 31;
    int pair = warp >> 1, kh = warp & 1, barid = pair + 1;
    int gp = blockIdx.x * 4 + pair, np = gridDim.x * 4;
    int ntask = NN * halves, Ct = halves << 6;
    int cin = kh * 32 + lane;
    bool hasT = (stats_off >= 0);
    float s = 1.f, t = 0.f;
    if (hasT) {
        double mu = g_sum[stats_off + cin] / (double)NN;
        double va = g_sumsq[stats_off + cin] / (double)NN - mu * mu;
        s = gamma[cin] * rsqrtf((float)va + BNEPS);
        t = beta[cin] - (float)mu * s;
    }
    u64 Wreg[34];
    int curhalf = -1, par = 0;
    for (int task = gp; task < ntask; task += np) {
        int half = task >> 16, node = task & (NN - 1);
        if (half != curhalf) {
            curhalf = half;
            const float* W = half ? Wb : Wa;
            #pragma unroll
            for (int j = 0; j < 32; j++)
                Wreg[j] = *(const u64*)(W + (size_t)(kh * 32 + j) * 64 + 2 * lane);
            if (kh) {
                Wreg[32] = *(const u64*)(W + (size_t)64 * 64 + 2 * lane);
                Wreg[33] = *(const u64*)(W + (size_t)65 * 64 + 2 * lane);
            }
        }
        float av = X[(size_t)node * 64 + cin];
        if (hasT) av = fmaxf(fmaf(av, s, t), 0.f);
        dup[warp][par][lane] = pk2(av, av);
        __syncwarp();
        u64 a0 = 0, a1 = 0, a2 = 0, a3 = 0;
        #pragma unroll
        for (int j = 0; j < 32; j += 4) {
            a0 = f2fma(Wreg[j],     dup[warp][par][j],     a0);
            a1 = f2fma(Wreg[j + 1], dup[warp][par][j + 1], a1);
            a2 = f2fma(Wreg[j + 2], dup[warp][par][j + 2], a2);
            a3 = f2fma(Wreg[j + 3], dup[warp][par][j + 3], a3);
        }
        u64 r = f2add(f2add(a0, a1), f2add(a2, a3));
        if (kh) {
            float2 p = *(const float2*)(pos + (size_t)node * 2);
            r = f2fma(Wreg[32], pk2(p.x, p.x), r);
            r = f2fma(Wreg[33], pk2(p.y, p.y), r);
            pbuf[pair][par][lane] = r;
        }
        asm volatile("bar.sync %0, 64;" :: "r"(barid) : "memory");
        if (!kh) {
            r = f2add(r, pbuf[pair][par][lane]);
            float rx, ry; upk2(r, rx, ry);
            float2 o; o.x = rx; o.y = ry;
            *(float2*)(Z + (size_t)node * Ct + (half << 6) + 2 * lane) = o;
        }
        par ^= 1;
    }
}

// ---------------- gather-max of one 64-ch half (unroll 8), minus pos term ----------------
__device__ __forceinline__ float2 gather_max(
    const float* __restrict__ zr, int node, int Ct,
    const float* __restrict__ Wl, const float* __restrict__ pos, int lane)
{
    float2 m = *(const float2*)(zr + (size_t)node * Ct);
    int beg = g_rowptr[node], end = g_rowptr[node + 1];
    int j = beg;
    for (; j + 8 <= end; j += 8) {
        int i0 = g_col[j], i1 = g_col[j+1], i2 = g_col[j+2], i3 = g_col[j+3];
        int i4 = g_col[j+4], i5 = g_col[j+5], i6 = g_col[j+6], i7 = g_col[j+7];
        float2 v0 = *(const float2*)(zr + (size_t)i0 * Ct);
        float2 v1 = *(const float2*)(zr + (size_t)i1 * Ct);
        float2 v2 = *(const float2*)(zr + (size_t)i2 * Ct);
        float2 v3 = *(const float2*)(zr + (size_t)i3 * Ct);
        float2 v4 = *(const float2*)(zr + (size_t)i4 * Ct);
        float2 v5 = *(const float2*)(zr + (size_t)i5 * Ct);
        float2 v6 = *(const float2*)(zr + (size_t)i6 * Ct);
        float2 v7 = *(const float2*)(zr + (size_t)i7 * Ct);
        float ax = fmaxf(fmaxf(v0.x, v1.x), fmaxf(v2.x, v3.x));
        float bx = fmaxf(fmaxf(v4.x, v5.x), fmaxf(v6.x, v7.x));
        float ay = fmaxf(fmaxf(v0.y, v1.y), fmaxf(v2.y, v3.y));
        float by = fmaxf(fmaxf(v4.y, v5.y), fmaxf(v6.y, v7.y));
        m.x = fmaxf(m.x, fmaxf(ax, bx));
        m.y = fmaxf(m.y, fmaxf(ay, by));
    }
    for (; j < end; j++) {
        int s = g_col[j];
        float2 v = *(const float2*)(zr + (size_t)s * Ct);
        m.x = fmaxf(m.x, v.x); m.y = fmaxf(m.y, v.y);
    }
    float2 w0 = *(const float2*)(Wl + 64 * 64 + 2 * lane);
    float2 w1 = *(const float2*)(Wl + 65 * 64 + 2 * lane);
    float2 p = *(const float2*)(pos + (size_t)node * 2);
    m.x -= p.x * w0.x + p.y * w1.x;
    m.y -= p.x * w0.y + p.y * w1.y;
    return m;
}

// ---------------- segment max (low-reg, high-occ) ----------------
// Ct = Z row stride; nh = halves to process; Mstride = M row stride.
__global__ void segmax_kernel(
    const float* __restrict__ Z, const float* __restrict__ pos,
    const float* __restrict__ Wa, const float* __restrict__ Wb,
    float* __restrict__ M, int Ct, int nh, int Mstride)
{
    int gw = (blockIdx.x * blockDim.x + threadIdx.x) >> 5;
    int lane = threadIdx.x & 31;
    int nw = (gridDim.x * blockDim.x) >> 5;
    int ntask = NN * nh;
    for (int task = gw; task < ntask; task += nw) {
        int half = task >> 16;
        int node = task & (NN - 1);
        const float* zr = Z + (half << 6) + 2 * lane;
        const float* Wl = half ? Wb : Wa;
        float2 m = gather_max(zr, node, Ct, Wl, pos, lane);
        *(float2*)(M + (size_t)node * Mstride + (half << 6) + 2 * lane) = m;
    }
}

// ---------------- split-k m-GEMM (COUT=64 per half, dual-output, BN stats) ----------------
__global__ void __launch_bounds__(256, 2) mgemm_kernel(
    const float* __restrict__ M, int Cin,
    const float* __restrict__ W2a, const float* __restrict__ W2b,
    float* __restrict__ OUTa, float* __restrict__ OUTb,
    int statsA, int statsB, int halves)
{
    __shared__ u64 dup[8][2][32];
    __shared__ u64 pbuf[4][2][32];
    int tid = threadIdx.x, warp = tid >> 5, lane = tid & 31;
    int pair = warp >> 1, kh = warp & 1, barid = pair + 1;
    int gp = blockIdx.x * 4 + pair, np = gridDim.x * 4;
    int ntask = NN * halves;
    u64 Wreg[32];
    float* OUT = OUTa;
    int curhalf = -1, curstats = -1, par = 0;
    float ls0 = 0.f, lq0 = 0.f, ls1 = 0.f, lq1 = 0.f;
    for (int task = gp; task < ntask; task += np) {
        int half = task >> 16, node = task & (NN - 1);
        if (half != curhalf) {
            if (!kh && curstats >= 0) {
                atomicAdd(&g_sum[curstats + 2 * lane],     (double)ls0);
                atomicAdd(&g_sum[curstats + 2 * lane + 1], (double)ls1);
                atomicAdd(&g_sumsq[curstats + 2 * lane],     (double)lq0);
                atomicAdd(&g_sumsq[curstats + 2 * lane + 1], (double)lq1);
                ls0 = lq0 = ls1 = lq1 = 0.f;
            }
            curhalf = half;
            const float* W2 = half ? W2b : W2a;
            #pragma unroll
            for (int j = 0; j < 32; j++)
                Wreg[j] = *(const u64*)(W2 + (size_t)(kh * 32 + j) * 64 + 2 * lane);
            OUT = half ? OUTb : OUTa;
            curstats = half ? statsB : statsA;
        }
        float av = M[(size_t)node * Cin + half * 64 + kh * 32 + lane];
        dup[warp][par][lane] = pk2(av, av);
        __syncwarp();
        u64 a0 = 0, a1 = 0, a2 = 0, a3 = 0;
        #pragma unroll
        for (int j = 0; j < 32; j += 4) {
            a0 = f2fma(Wreg[j],     dup[warp][par][j],     a0);
            a1 = f2fma(Wreg[j + 1], dup[warp][par][j + 1], a1);
            a2 = f2fma(Wreg[j + 2], dup[warp][par][j + 2], a2);
            a3 = f2fma(Wreg[j + 3], dup[warp][par][j + 3], a3);
        }
        u64 r = f2add(f2add(a0, a1), f2add(a2, a3));
        if (kh) pbuf[pair][par][lane] = r;
        asm volatile("bar.sync %0, 64;" :: "r"(barid) : "memory");
        if (!kh) {
            r = f2add(r, pbuf[pair][par][lane]);
            float rx, ry; upk2(r, rx, ry);
            ls0 += rx; lq0 += rx * rx;
            ls1 += ry; lq1 += ry * ry;
            float2 o; o.x = rx; o.y = ry;
            *(float2*)(OUT + (size_t)node * 64 + 2 * lane) = o;
        }
        par ^= 1;
    }
    if (!kh && curstats >= 0) {
        atomicAdd(&g_sum[curstats + 2 * lane],     (double)ls0);
        atomicAdd(&g_sum[curstats + 2 * lane + 1], (double)ls1);
        atomicAdd(&g_sumsq[curstats + 2 * lane],     (double)lq0);
        atomicAdd(&g_sumsq[curstats + 2 * lane + 1], (double)lq1);
    }
}

// ---------------- split-k cls GEMM (COUT=101, two output halves) ----------------
__global__ void __launch_bounds__(256, 2) clsgemm_kernel(
    const float* __restrict__ M /*stride 64*/, const float* __restrict__ W /*64x101*/,
    const float* __restrict__ bias, float* __restrict__ OUT)
{
    __shared__ u64 dup[8][2][32];
    __shared__ u64 pbuf[4][2][32];
    int tid = threadIdx.x, warp = tid >> 5, lane = tid & 31;
    int pair = warp >> 1, kh = warp & 1, barid = pair + 1;
    int gp = blockIdx.x * 4 + pair, np = gridDim.x * 4;
    int ntask = NN * 2;
    u64 Wreg[32];
    int curo = -1, par = 0;
    int c0 = 0; bool v0 = false, v1 = false;
    float bx = 0.f, by = 0.f;
    for (int task = gp; task < ntask; task += np) {
        int oh = task >> 16, node = task & (NN - 1);
        if (oh != curo) {
            curo = oh;
            c0 = oh * 64 + 2 * lane;
            v0 = (c0 < CC); v1 = (c0 + 1 < CC);
            #pragma unroll
            for (int j = 0; j < 32; j++) {
                float wx = v0 ? W[(size_t)(kh * 32 + j) * CC + c0] : 0.f;
                float wy = v1 ? W[(size_t)(kh * 32 + j) * CC + c0 + 1] : 0.f;
                Wreg[j] = pk2(wx, wy);
            }
            bx = v0 ? bias[c0] : 0.f;
            by = v1 ? bias[c0 + 1] : 0.f;
        }
        float av = M[(size_t)node * 64 + kh * 32 + lane];
        dup[warp][par][lane] = pk2(av, av);
        __syncwarp();
        u64 a0 = 0, a1 = 0, a2 = 0, a3 = 0;
        #pragma unroll
        for (int j = 0; j < 32; j += 4) {
            a0 = f2fma(Wreg[j],     dup[warp][par][j],     a0);
            a1 = f2fma(Wreg[j + 1], dup[warp][par][j + 1], a1);
            a2 = f2fma(Wreg[j + 2], dup[warp][par][j + 2], a2);
            a3 = f2fma(Wreg[j + 3], dup[warp][par][j + 3], a3);
        }
        u64 r = f2add(f2add(a0, a1), f2add(a2, a3));
        if (kh) pbuf[pair][par][lane] = r;
        asm volatile("bar.sync %0, 64;" :: "r"(barid) : "memory");
        if (!kh) {
            r = f2add(r, pbuf[pair][par][lane]);
            float rx, ry; upk2(r, rx, ry);
            rx += bx; ry += by;
            if (v0) OUT[(size_t)node * CC + c0] = rx;
            if (v1) OUT[(size_t)node * CC + c0 + 1] = ry;
        }
        par ^= 1;
    }
}

// ---------------- FUSED segmax + 4-channel head (reg) ----------------
__global__ void fseghead4_kernel(
    const float* __restrict__ Z, const float* __restrict__ pos,
    const float* __restrict__ Wl, const float* __restrict__ W2 /*[64,4]*/,
    const float* __restrict__ bias, float* __restrict__ OUT)
{
    int gw = (blockIdx.x * blockDim.x + threadIdx.x) >> 5;
    int lane = threadIdx.x & 31;
    if (gw >= NN) return;
    float4 wa = *(const float4*)(W2 + (size_t)(2 * lane) * 4);
    float4 wb = *(const float4*)(W2 + (size_t)(2 * lane + 1) * 4);
    const float* zr = Z + 2 * lane;
    float2 m = gather_max(zr, gw, 64, Wl, pos, lane);
    float p0 = m.x * wa.x + m.y * wb.x;
    float p1 = m.x * wa.y + m.y * wb.y;
    float p2 = m.x * wa.z + m.y * wb.z;
    float p3 = m.x * wa.w + m.y * wb.w;
    #pragma unroll
    for (int o = 16; o > 0; o >>= 1) {
        p0 += __shfl_xor_sync(0xffffffff, p0, o);
        p1 += __shfl_xor_sync(0xffffffff, p1, o);
        p2 += __shfl_xor_sync(0xffffffff, p2, o);
        p3 += __shfl_xor_sync(0xffffffff, p3, o);
    }
    if (lane == 0) {
        float4 r;
        r.x = p0 + bias[0]; r.y = p1 + bias[1];
        r.z = p2 + bias[2]; r.w = p3 + bias[3];
        *(float4*)(OUT + (size_t)gw * 4) = r;
    }
}

// ---------------- FUSED segmax + 1-channel head (obj; gathers Z half b, Ct=128) ----------------
__global__ void fseghead1_kernel(
    const float* __restrict__ Z, const float* __restrict__ pos,
    const float* __restrict__ Wl, const float* __restrict__ W2 /*[64,1]*/,
    const float* __restrict__ bias, float* __restrict__ OUT)
{
    int gw = (blockIdx.x * blockDim.x + threadIdx.x) >> 5;
    int lane = threadIdx.x & 31;
    if (gw >= NN) return;
    float w0 = W2[2 * lane], w1 = W2[2 * lane + 1];
    const float* zr = Z + 64 + 2 * lane;
    float2 m = gather_max(zr, gw, 128, Wl, pos, lane);
    float p0 = m.x * w0 + m.y * w1;
    #pragma unroll
    for (int o = 16; o > 0; o >>= 1)
        p0 += __shfl_xor_sync(0xffffffff, p0, o);
    if (lane == 0) OUT[gw] = p0 + bias[0];
}

// ---------------- host orchestration ----------------
static void* symaddr(const void* symbol) {
    void* p = nullptr;
    cudaGetSymbolAddress(&p, symbol);
    return p;
}

extern "C" void kernel_launch(void* const* d_in, const int* in_sizes, int n_in,
                              void* d_out, int out_size)
{
    const float* x   = (const float*)d_in[0];
    const float* pos = (const float*)d_in[1];
    const int*   ei  = (const int*)d_in[2];
    const float* W11 = (const float*)d_in[3];  const float* W12 = (const float*)d_in[4];
    const float* g1  = (const float*)d_in[5];  const float* b1  = (const float*)d_in[6];
    const float* W21 = (const float*)d_in[7];  const float* W22 = (const float*)d_in[8];
    const float* g2  = (const float*)d_in[9];  const float* b2  = (const float*)d_in[10];
    const float* W31 = (const float*)d_in[11]; const float* W32 = (const float*)d_in[12];
    const float* g3  = (const float*)d_in[13]; const float* b3  = (const float*)d_in[14];
    const float* Wr1 = (const float*)d_in[15]; const float* Wr2 = (const float*)d_in[16];
    const float* br2 = (const float*)d_in[17];
    const float* Wc1 = (const float*)d_in[18]; const float* Wc2 = (const float*)d_in[19];
    const float* bc2 = (const float*)d_in[20];
    const float* Wo1 = (const float*)d_in[21]; const float* Wo2 = (const float*)d_in[22];
    const float* bo2 = (const float*)d_in[23];
    float* out = (float*)d_out;

    const int* src = ei;
    const int* dst = ei + EE;

    float* Z  = (float*)symaddr(g_z);
    float* M  = (float*)symaddr(g_m);
    float* H1 = (float*)symaddr(g_h1);
    float* H2 = (float*)symaddr(g_h2);
    float* H3 = (float*)symaddr(g_h3);

    const int GB = 296;

    // ---- CSR build (zgemm1 at slot 4 for ncu capture) ----
    zero_kernel<<<NN / 256, 256>>>();
    deg_kernel<<<EE / 256, 256>>>(dst);
    scan1_kernel<<<256, 256>>>();
    zgemm_kernel<<<GB, 256>>>(x, pos, W11, nullptr, nullptr, nullptr, -1, Z, 1);  // slot 4
    scan23_kernel<<<256, 256>>>();
    fill_kernel<<<EE / 256, 256>>>(src, dst);

    // ---- conv1 ----
    segmax_kernel<<<NN / 8, 256>>>(Z, pos, W11, nullptr, M, 64, 1, 64);
    mgemm_kernel<<<GB, 256>>>(M, 64, W12, nullptr, H1, nullptr, 0, -1, 1);

    // ---- conv2 + conv3 (x1 = relu(bn1(h1)) inline) ----
    zgemm_kernel<<<GB, 256>>>(H1, pos, W21, W31, g1, b1, 0, Z, 2);
    segmax_kernel<<<NN * 2 / 8, 256>>>(Z, pos, W21, W31, M, 128, 2, 128);
    mgemm_kernel<<<GB, 256>>>(M, 128, W22, W32, H2, H3, 64, 128, 2);

    // ---- reg head (x2 = relu(bn2(h2)) inline) ----
    zgemm_kernel<<<GB, 256>>>(H2, pos, Wr1, nullptr, g2, b2, 64, Z, 1);
    fseghead4_kernel<<<NN / 8, 256>>>(Z, pos, Wr1, Wr2, br2, out + (size_t)NN * CC);

    // ---- cls + obj heads (x3 = relu(bn3(h3)) inline) ----
    zgemm_kernel<<<GB, 256>>>(H3, pos, Wc1, Wo1, g3, b3, 128, Z, 2);
    segmax_kernel<<<NN / 8, 256>>>(Z, pos, Wc1, nullptr, M, 128, 1, 64);  // cls half only
    clsgemm_kernel<<<GB, 256>>>(M, Wc2, bc2, out);
    fseghead1_kernel<<<NN / 8, 256>>>(Z, pos, Wo1, Wo2, bo2, out + (size_t)NN * (CC + 4));

    (void)in_sizes; (void)n_in; (void)out_size;
}